// round 17
// baseline (speedup 1.0000x reference)
#include <cuda_runtime.h>
#include <cuda_bf16.h>
#include <math.h>
#include <cstdint>

#define B_ 64
#define H_ 1024

// ---------------------------------------------------------------------------
// Scratch (__device__ globals; allocation-free rule)
// ---------------------------------------------------------------------------
__device__ float g_s2[18][B_ * H_]; // 18 split-K partial pre-activations
__device__ float g_ep[8][B_ * H_];  // split-K partials of e = k_t @ We
__device__ float4 g_gate[B_ * H_];  // (ft, it*vt, ot, nt) per row
__device__ float g_kb[B_ * H_];     // k_t + bk
__device__ float g_qb[B_ * H_];     // q_t + bq

// ---------------------------------------------------------------------------
// helpers
// ---------------------------------------------------------------------------
__device__ __forceinline__ uint32_t smem_u32(const void* p) {
    uint32_t a;
    asm("{ .reg .u64 t; cvta.to.shared.u64 t, %1; cvt.u32.u64 %0, t; }" : "=r"(a) : "l"(p));
    return a;
}

__device__ __forceinline__ void split2(float v0, float v1, uint32_t& hi, uint32_t& lo) {
    __nv_bfloat16 h0 = __float2bfloat16_rn(v0);
    __nv_bfloat16 h1 = __float2bfloat16_rn(v1);
    float l0 = v0 - __bfloat162float(h0);
    float l1 = v1 - __bfloat162float(h1);
    __nv_bfloat162 hp; hp.x = h0; hp.y = h1;
    __nv_bfloat162 lp = __floats2bfloat162_rn(l0, l1);
    hi = *(uint32_t*)&hp;
    lo = *(uint32_t*)&lp;
}

#define LDSM_X4(r0, r1, r2, r3, addr) \
    asm volatile("ldmatrix.sync.aligned.m8n8.x4.shared.b16 {%0,%1,%2,%3}, [%4];" \
        : "=r"(r0), "=r"(r1), "=r"(r2), "=r"(r3) : "r"(addr))
#define LDSM_X4T(r0, r1, r2, r3, addr) \
    asm volatile("ldmatrix.sync.aligned.m8n8.x4.trans.shared.b16 {%0,%1,%2,%3}, [%4];" \
        : "=r"(r0), "=r"(r1), "=r"(r2), "=r"(r3) : "r"(addr))
#define MMA16816(c, a0, a1, a2, a3, b0, b1) \
    asm volatile("mma.sync.aligned.m16n8k16.row.col.f32.bf16.bf16.f32 " \
        "{%0,%1,%2,%3}, {%4,%5,%6,%7}, {%8,%9}, {%0,%1,%2,%3};" \
        : "+f"(c[0]), "+f"(c[1]), "+f"(c[2]), "+f"(c[3]) \
        : "r"(a0), "r"(a1), "r"(a2), "r"(a3), "r"(b0), "r"(b1))

// ---------------------------------------------------------------------------
// Kernel 1: split-K partial GEMMs, HMMA bf16 3-term (R15-validated core).
// mode 0: k/q jobs {12,13,16,17}, grid (16, 4)
// mode 1: gate jobs {0..11,14,15}, grid (8, 14), n-tile offset nofs
// ---------------------------------------------------------------------------
#define AROW 144
#define WROW 144
#define OFF_AH 0
#define OFF_AL 9216
#define OFF_WH 18432
#define OFF_WL 27648
#define STG    36864
#define SMEM_TOTAL (2 * STG)

__global__ __launch_bounds__(256, 2) void mma_kernel(
    int mode, int nofs,
    const float* __restrict__ x, const float* __restrict__ h,
    const float* __restrict__ Wi, const float* __restrict__ Wf,
    const float* __restrict__ Wo, const float* __restrict__ Wk,
    const float* __restrict__ Wv, const float* __restrict__ Wq)
{
    extern __shared__ __align__(16) char smem[];
    const uint32_t sb = smem_u32(smem);
    const int tid = threadIdx.x;
    const int wid = tid >> 5;
    const int lane = tid & 31;

    int pj;
    if (mode == 0) {
        const int jm[4] = {12, 13, 16, 17};
        pj = jm[blockIdx.y];
    } else {
        const int y = blockIdx.y;
        pj = (y < 12) ? y : y + 2;
    }
    const int job = pj >> 1;
    const int ksp = pj & 1;
    const int n0 = (nofs + blockIdx.x) * 64;

    const float *A, *W;
    switch (job) {
        case 0: A = x; W = Wi;                          break;
        case 1: A = h; W = Wi + (size_t)1024 * 1024;    break;
        case 2: A = x; W = Wf;                          break;
        case 3: A = h; W = Wf + (size_t)1024 * 1024;    break;
        case 4: A = x; W = Wo;                          break;
        case 5: A = h; W = Wo + (size_t)1024 * 1024;    break;
        case 6: A = x; W = Wk;                          break;
        case 7: A = x; W = Wv;                          break;
        default: A = h; W = Wq;                         break;
    }
    A += ksp * 512;
    W += (size_t)(ksp * 512) * H_;
    float* out = g_s2[pj];

    const int arow = tid >> 2;
    const int acb  = (tid & 3) * 16;
    const int wrow = tid >> 2;
    const int wcb  = (tid & 3) * 16;

    const int kh = wid >> 2;
    const int mw = (wid >> 1) & 1;
    const int nw = wid & 1;
    const int m0 = mw * 32;
    const uint32_t a_off = (uint32_t)(m0 + (lane & 15)) * AROW
                         + (uint32_t)((lane >> 4) * 8 + kh * 32) * 2;
    const uint32_t b_off = (uint32_t)((lane & 7) + ((lane >> 3) & 1) * 8 + kh * 32) * WROW
                         + (uint32_t)((lane >> 4) * 8 + nw * 32) * 2;

    float acc[8][4] = {};
    float4 pA[4], pW[4];

    #pragma unroll
    for (int j = 0; j < 4; j++) {
        pA[j] = *(const float4*)(A + (size_t)arow * H_ + acb + j * 4);
        pW[j] = *(const float4*)(W + (size_t)wrow * H_ + n0 + wcb + j * 4);
    }
    {
        char* st = smem;
        #pragma unroll
        for (int j = 0; j < 4; j++) {
            uint32_t h0, l0, h1, l1;
            split2(pA[j].x, pA[j].y, h0, l0);
            split2(pA[j].z, pA[j].w, h1, l1);
            const uint32_t ao = (uint32_t)arow * AROW + (uint32_t)(acb + j * 4) * 2;
            *(uint2*)(st + OFF_AH + ao) = make_uint2(h0, h1);
            *(uint2*)(st + OFF_AL + ao) = make_uint2(l0, l1);
            split2(pW[j].x, pW[j].y, h0, l0);
            split2(pW[j].z, pW[j].w, h1, l1);
            const uint32_t wo = (uint32_t)wrow * WROW + (uint32_t)(wcb + j * 4) * 2;
            *(uint2*)(st + OFF_WH + wo) = make_uint2(h0, h1);
            *(uint2*)(st + OFF_WL + wo) = make_uint2(l0, l1);
        }
    }
    __syncthreads();

    #pragma unroll 1
    for (int t = 0; t < 8; t++) {
        const int s = t & 1;

        if (t < 7) {
            const int kc = (t + 1) * 64;
            #pragma unroll
            for (int j = 0; j < 4; j++) {
                pA[j] = *(const float4*)(A + (size_t)arow * H_ + kc + acb + j * 4);
                pW[j] = *(const float4*)(W + (size_t)(kc + wrow) * H_ + n0 + wcb + j * 4);
            }
        }

        {
            const uint32_t ah = sb + s * STG + OFF_AH + a_off;
            const uint32_t al = sb + s * STG + OFF_AL + a_off;
            const uint32_t wh = sb + s * STG + OFF_WH + b_off;
            const uint32_t wl = sb + s * STG + OFF_WL + b_off;
            #pragma unroll
            for (int ks = 0; ks < 2; ks++) {
                const uint32_t ko2 = ks * 32;
                const uint32_t kor = ks * 16 * WROW;
                uint32_t a0h[4], a0l[4], a1h[4], a1l[4];
                LDSM_X4(a0h[0], a0h[1], a0h[2], a0h[3], ah + ko2);
                LDSM_X4(a0l[0], a0l[1], a0l[2], a0l[3], al + ko2);
                LDSM_X4(a1h[0], a1h[1], a1h[2], a1h[3], ah + 16 * AROW + ko2);
                LDSM_X4(a1l[0], a1l[1], a1l[2], a1l[3], al + 16 * AROW + ko2);
                #pragma unroll
                for (int np = 0; np < 2; np++) {
                    const uint32_t no = np * 32;
                    uint32_t b0, b1, b2, b3, f0, f1, f2, f3;
                    LDSM_X4T(b0, b1, b2, b3, wh + kor + no);
                    LDSM_X4T(f0, f1, f2, f3, wl + kor + no);
                    MMA16816(acc[np * 2],     a0h[0], a0h[1], a0h[2], a0h[3], b0, b1);
                    MMA16816(acc[np * 2],     a0h[0], a0h[1], a0h[2], a0h[3], f0, f1);
                    MMA16816(acc[np * 2],     a0l[0], a0l[1], a0l[2], a0l[3], b0, b1);
                    MMA16816(acc[np * 2 + 1], a0h[0], a0h[1], a0h[2], a0h[3], b2, b3);
                    MMA16816(acc[np * 2 + 1], a0h[0], a0h[1], a0h[2], a0h[3], f2, f3);
                    MMA16816(acc[np * 2 + 1], a0l[0], a0l[1], a0l[2], a0l[3], b2, b3);
                    MMA16816(acc[4 + np * 2],     a1h[0], a1h[1], a1h[2], a1h[3], b0, b1);
                    MMA16816(acc[4 + np * 2],     a1h[0], a1h[1], a1h[2], a1h[3], f0, f1);
                    MMA16816(acc[4 + np * 2],     a1l[0], a1l[1], a1l[2], a1l[3], b0, b1);
                    MMA16816(acc[4 + np * 2 + 1], a1h[0], a1h[1], a1h[2], a1h[3], b2, b3);
                    MMA16816(acc[4 + np * 2 + 1], a1h[0], a1h[1], a1h[2], a1h[3], f2, f3);
                    MMA16816(acc[4 + np * 2 + 1], a1l[0], a1l[1], a1l[2], a1l[3], b2, b3);
                }
            }
        }

        if (t < 7) {
            char* st = smem + (s ^ 1) * STG;
            #pragma unroll
            for (int j = 0; j < 4; j++) {
                uint32_t h0, l0, h1, l1;
                split2(pA[j].x, pA[j].y, h0, l0);
                split2(pA[j].z, pA[j].w, h1, l1);
                const uint32_t ao = (uint32_t)arow * AROW + (uint32_t)(acb + j * 4) * 2;
                *(uint2*)(st + OFF_AH + ao) = make_uint2(h0, h1);
                *(uint2*)(st + OFF_AL + ao) = make_uint2(l0, l1);
                split2(pW[j].x, pW[j].y, h0, l0);
                split2(pW[j].z, pW[j].w, h1, l1);
                const uint32_t wo = (uint32_t)wrow * WROW + (uint32_t)(wcb + j * 4) * 2;
                *(uint2*)(st + OFF_WH + wo) = make_uint2(h0, h1);
                *(uint2*)(st + OFF_WL + wo) = make_uint2(l0, l1);
            }
        }
        __syncthreads();
    }

    __syncthreads();
    float* red = (float*)smem;
    const int slot = ((mw * 2 + nw) * 32 + lane) * 36;
    if (kh == 1) {
        #pragma unroll
        for (int na = 0; na < 8; na++)
            *(float4*)(red + slot + na * 4) =
                make_float4(acc[na][0], acc[na][1], acc[na][2], acc[na][3]);
    }
    __syncthreads();
    if (kh == 0) {
        const int r0 = m0 + (lane >> 2);
        const int c0 = (lane & 3) * 2;
        #pragma unroll
        for (int mt = 0; mt < 2; mt++) {
            #pragma unroll
            for (int np = 0; np < 2; np++) {
                #pragma unroll
                for (int hf = 0; hf < 2; hf++) {
                    const int sI = mt * 4 + np * 2 + hf;
                    float4 o = *(const float4*)(red + slot + sI * 4);
                    const int cg = n0 + nw * 32 + np * 16 + hf * 8 + c0;
                    const int rg = r0 + mt * 16;
                    *(float2*)(out + (size_t)rg * H_ + cg) =
                        make_float2(acc[sI][0] + o.x, acc[sI][1] + o.y);
                    *(float2*)(out + (size_t)(rg + 8) * H_ + cg) =
                        make_float2(acc[sI][2] + o.z, acc[sI][3] + o.w);
                }
            }
        }
    }
}

// ---------------------------------------------------------------------------
// Kernel 2: e partials. A = (g_s2[12]+g_s2[13] + bk), W = We. split-K=8.
// ---------------------------------------------------------------------------
__global__ __launch_bounds__(256, 1) void egemm_kernel(
    const float* __restrict__ We, const float* __restrict__ bk)
{
    constexpr int TK = 32;
    __shared__ __align__(16) float As[2][TK][64 + 4];
    __shared__ __align__(16) float Ws[2][TK][64 + 4];

    const float* A0 = &g_s2[12][0];
    const float* A1 = &g_s2[13][0];
    float* out = &g_ep[blockIdx.y][0];
    const int kbase = blockIdx.y * 128;
    const int n0 = blockIdx.x * 64;
    const int t  = threadIdx.x;
    const int tr = t >> 4;
    const int tc = t & 15;

    const int arow = t >> 3;
    const int akq  = (t & 7) << 2;
    const int wr   = t >> 4;
    const int wc   = (t & 15) << 2;

    float acc[4][4] = {};
    float4 pa0, pa1, pc0, pc1, pw0, pw1, pb;

    pa0 = *(const float4*)(A0 + arow * H_ + kbase + akq);
    pc0 = *(const float4*)(A1 + arow * H_ + kbase + akq);
    pa1 = *(const float4*)(A0 + (arow + 32) * H_ + kbase + akq);
    pc1 = *(const float4*)(A1 + (arow + 32) * H_ + kbase + akq);
    pb  = *(const float4*)(bk + kbase + akq);
    pw0 = *(const float4*)(We + (size_t)(kbase + wr) * H_ + n0 + wc);
    pw1 = *(const float4*)(We + (size_t)(kbase + wr + 16) * H_ + n0 + wc);
    As[0][akq + 0][arow] = pa0.x + pc0.x + pb.x;
    As[0][akq + 1][arow] = pa0.y + pc0.y + pb.y;
    As[0][akq + 2][arow] = pa0.z + pc0.z + pb.z;
    As[0][akq + 3][arow] = pa0.w + pc0.w + pb.w;
    As[0][akq + 0][arow + 32] = pa1.x + pc1.x + pb.x;
    As[0][akq + 1][arow + 32] = pa1.y + pc1.y + pb.y;
    As[0][akq + 2][arow + 32] = pa1.z + pc1.z + pb.z;
    As[0][akq + 3][arow + 32] = pa1.w + pc1.w + pb.w;
    *(float4*)&Ws[0][wr][wc]      = pw0;
    *(float4*)&Ws[0][wr + 16][wc] = pw1;
    __syncthreads();

    #pragma unroll 1
    for (int tile = 0; tile < 4; tile++) {
        const int cur = tile & 1;
        const int nxt = cur ^ 1;
        if (tile + 1 < 4) {
            const int k0n = kbase + (tile + 1) * TK;
            pa0 = *(const float4*)(A0 + arow * H_ + k0n + akq);
            pc0 = *(const float4*)(A1 + arow * H_ + k0n + akq);
            pa1 = *(const float4*)(A0 + (arow + 32) * H_ + k0n + akq);
            pc1 = *(const float4*)(A1 + (arow + 32) * H_ + k0n + akq);
            pb  = *(const float4*)(bk + k0n + akq);
            pw0 = *(const float4*)(We + (size_t)(k0n + wr) * H_ + n0 + wc);
            pw1 = *(const float4*)(We + (size_t)(k0n + wr + 16) * H_ + n0 + wc);
        }
        #pragma unroll
        for (int kk = 0; kk < TK; kk++) {
            float4 a = *(const float4*)&As[cur][kk][tr << 2];
            float4 b = *(const float4*)&Ws[cur][kk][tc << 2];
            #pragma unroll
            for (int i = 0; i < 4; i++) {
                float av = (i == 0) ? a.x : (i == 1) ? a.y : (i == 2) ? a.z : a.w;
                acc[i][0] = fmaf(av, b.x, acc[i][0]);
                acc[i][1] = fmaf(av, b.y, acc[i][1]);
                acc[i][2] = fmaf(av, b.z, acc[i][2]);
                acc[i][3] = fmaf(av, b.w, acc[i][3]);
            }
        }
        if (tile + 1 < 4) {
            As[nxt][akq + 0][arow] = pa0.x + pc0.x + pb.x;
            As[nxt][akq + 1][arow] = pa0.y + pc0.y + pb.y;
            As[nxt][akq + 2][arow] = pa0.z + pc0.z + pb.z;
            As[nxt][akq + 3][arow] = pa0.w + pc0.w + pb.w;
            As[nxt][akq + 0][arow + 32] = pa1.x + pc1.x + pb.x;
            As[nxt][akq + 1][arow + 32] = pa1.y + pc1.y + pb.y;
            As[nxt][akq + 2][arow + 32] = pa1.z + pc1.z + pb.z;
            As[nxt][akq + 3][arow + 32] = pa1.w + pc1.w + pb.w;
            *(float4*)&Ws[nxt][wr][wc]      = pw0;
            *(float4*)&Ws[nxt][wr + 16][wc] = pw1;
        }
        __syncthreads();
    }

    #pragma unroll
    for (int i = 0; i < 4; i++) {
        int row = (tr << 2) + i;
        float4 v = make_float4(acc[i][0], acc[i][1], acc[i][2], acc[i][3]);
        *(float4*)(out + row * H_ + n0 + (tc << 2)) = v;
    }
}

// ---------------------------------------------------------------------------
// Kernel 2a: fold k/q partial pairs + biases into g_kb/g_qb (full vectors,
// needed globally by both update halves).
// ---------------------------------------------------------------------------
__global__ __launch_bounds__(256, 8) void kqbias_kernel(
    const float* __restrict__ bk, const float* __restrict__ bq)
{
    const int br = blockIdx.x * 256 + threadIdx.x;
    const int r = br & (H_ - 1);
    g_kb[br] = g_s2[12][br] + g_s2[13][br] + bk[r];
    g_qb[br] = g_s2[16][br] + g_s2[17][br] + bq[r];
}

// ---------------------------------------------------------------------------
// Kernel 2b: gates for a row-half: rows r in [half*512, half*512+512).
// ---------------------------------------------------------------------------
__device__ __forceinline__ float sigmoidf_(float z) {
    return 1.0f / (1.0f + expf(-z));
}

__global__ __launch_bounds__(256, 8) void gates_half_kernel(
    int half, const float* __restrict__ n_prev,
    const float* __restrict__ bi, const float* __restrict__ bf,
    const float* __restrict__ bo, const float* __restrict__ bv,
    const float* __restrict__ be, float* __restrict__ out_n)
{
    const int id = blockIdx.x * 256 + threadIdx.x;   // 0..32767
    const int b = id >> 9;
    const int r = half * 512 + (id & 511);
    const int br = b * H_ + r;

    const float it = sigmoidf_(g_s2[0][br] + g_s2[1][br] + g_s2[2][br] + g_s2[3][br] + bi[r]);
    const float ft = sigmoidf_(g_s2[4][br] + g_s2[5][br] + g_s2[6][br] + g_s2[7][br] + bf[r]);
    const float ot = sigmoidf_(g_s2[8][br] + g_s2[9][br] + g_s2[10][br] + g_s2[11][br] + bo[r]);
    const float vt = g_s2[14][br] + g_s2[15][br] + bv[r];

    float e = be[r];
    #pragma unroll
    for (int p = 0; p < 8; p++) e += g_ep[p][br];
    const float nt = fmaf(ft, n_prev[br], it * expf(e));

    out_n[br] = nt;
    g_gate[br] = make_float4(ft, it * vt, ot, nt);
}

// ---------------------------------------------------------------------------
// Kernel 3: C-stream update for a row-half (R11/R14-validated core).
// grid (32 rowgroups, 64 b).
// ---------------------------------------------------------------------------
__global__ __launch_bounds__(256, 4) void update3_half_kernel(
    int half, const float* __restrict__ C_prev,
    float* __restrict__ out_h, float* __restrict__ out_C)
{
    __shared__ __align__(16) float ks[H_];
    __shared__ __align__(16) float qs[H_];

    const int b    = blockIdx.y;
    const int tid  = threadIdx.x;
    const int wid  = tid >> 5;
    const int lane = tid & 31;

    {
        const int c = tid << 2;
        *(float4*)&ks[c] = *(const float4*)(&g_kb[b * H_] + c);
        *(float4*)&qs[c] = *(const float4*)(&g_qb[b * H_] + c);
    }
    __syncthreads();

    const int r0 = half * 512 + blockIdx.x * 16 + wid * 2;
    const int br0 = b * H_ + r0;
    const float4 g0 = g_gate[br0];
    const float4 g1 = g_gate[br0 + 1];
    const size_t base0 = (size_t)b * H_ * H_ + (size_t)r0 * H_;
    const size_t base1 = base0 + H_;

    float dA0 = 0.f, dB0 = 0.f, dA1 = 0.f, dB1 = 0.f;

    #pragma unroll 2
    for (int j = 0; j < 8; j++) {
        const int c = (lane << 2) + (j << 7);
        const float4 kv = *(const float4*)&ks[c];
        float4 cp0 = __ldcs((const float4*)(C_prev + base0 + c));
        float4 cp1 = __ldcs((const float4*)(C_prev + base1 + c));

        float4 ct0, ct1;
        ct0.x = fmaf(g0.x, cp0.x, g0.y * kv.x);
        ct0.y = fmaf(g0.x, cp0.y, g0.y * kv.y);
        ct0.z = fmaf(g0.x, cp0.z, g0.y * kv.z);
        ct0.w = fmaf(g0.x, cp0.w, g0.y * kv.w);
        ct1.x = fmaf(g1.x, cp1.x, g1.y * kv.x);
        ct1.y = fmaf(g1.x, cp1.y, g1.y * kv.y);
        ct1.z = fmaf(g1.x, cp1.z, g1.y * kv.z);
        ct1.w = fmaf(g1.x, cp1.w, g1.y * kv.w);
        __stcs((float4*)(out_C + base0 + c), ct0);
        __stcs((float4*)(out_C + base1 + c), ct1);

        const float4 qv = *(const float4*)&qs[c];
        dA0 = fmaf(ct0.x, qv.x, dA0);  dB0 = fmaf(ct0.y, qv.y, dB0);
        dA0 = fmaf(ct0.z, qv.z, dA0);  dB0 = fmaf(ct0.w, qv.w, dB0);
        dA1 = fmaf(ct1.x, qv.x, dA1);  dB1 = fmaf(ct1.y, qv.y, dB1);
        dA1 = fmaf(ct1.z, qv.z, dA1);  dB1 = fmaf(ct1.w, qv.w, dB1);
    }

    float dot0 = dA0 + dB0;
    float dot1 = dA1 + dB1;
    #pragma unroll
    for (int off = 16; off; off >>= 1) {
        dot0 += __shfl_xor_sync(0xffffffffu, dot0, off);
        dot1 += __shfl_xor_sync(0xffffffffu, dot1, off);
    }

    if (lane == 0) {
        out_h[br0]     = g0.z * dot0 / g0.w;
        out_h[br0 + 1] = g1.z * dot1 / g1.w;
    }
}

// ---------------------------------------------------------------------------
// Launch: software-pipelined phases with event fork/join (R12-validated
// capture-legal pattern; no W-traffic duplication this time).
// ---------------------------------------------------------------------------
extern "C" void kernel_launch(void* const* d_in, const int* in_sizes, int n_in,
                              void* d_out, int out_size)
{
    const float* x      = (const float*)d_in[0];
    const float* h_prev = (const float*)d_in[1];
    const float* C_prev = (const float*)d_in[2];
    const float* n_prev = (const float*)d_in[3];
    const float* Wi = (const float*)d_in[4];
    const float* bi = (const float*)d_in[5];
    const float* Wf = (const float*)d_in[6];
    const float* bf = (const float*)d_in[7];
    const float* Wo = (const float*)d_in[8];
    const float* bo = (const float*)d_in[9];
    const float* Wk = (const float*)d_in[10];
    const float* bk = (const float*)d_in[11];
    const float* Wv = (const float*)d_in[12];
    const float* bv = (const float*)d_in[13];
    const float* Wq = (const float*)d_in[14];
    const float* bq = (const float*)d_in[15];
    const float* We = (const float*)d_in[16];
    const float* be = (const float*)d_in[17];

    float* out_h = (float*)d_out;
    float* out_C = out_h + B_ * H_;
    float* out_n = out_C + (size_t)B_ * H_ * H_;

    static cudaStream_t s1 = nullptr;
    static cudaEvent_t evA = nullptr, evB = nullptr, evC = nullptr;
    if (!s1) {
        cudaStreamCreateWithFlags(&s1, cudaStreamNonBlocking);
        cudaEventCreateWithFlags(&evA, cudaEventDisableTiming);
        cudaEventCreateWithFlags(&evB, cudaEventDisableTiming);
        cudaEventCreateWithFlags(&evC, cudaEventDisableTiming);
        cudaFuncSetAttribute(mma_kernel,
                             cudaFuncAttributeMaxDynamicSharedMemorySize, SMEM_TOTAL);
    }

    // ---- Phase 1: k/q GEMMs (all n-tiles) + egemm + k/q bias fold ----
    mma_kernel<<<dim3(16, 4), 256, SMEM_TOTAL>>>(0, 0, x, h_prev, Wi, Wf, Wo, Wk, Wv, Wq);
    egemm_kernel<<<dim3(16, 8), 256>>>(We, bk);
    kqbias_kernel<<<256, 256>>>(bk, bq);

    // ---- Phase 2a: gate GEMMs n-tiles 0-7 + gates rows<512 ----
    mma_kernel<<<dim3(8, 14), 256, SMEM_TOTAL>>>(1, 0, x, h_prev, Wi, Wf, Wo, Wk, Wv, Wq);
    gates_half_kernel<<<128, 256>>>(0, n_prev, bi, bf, bo, bv, be, out_n);
    cudaEventRecord(evA, 0);

    // ---- fork: update rows<512 on s1, overlapping phase 2b ----
    cudaStreamWaitEvent(s1, evA, 0);
    update3_half_kernel<<<dim3(32, 64), 256, 0, s1>>>(0, C_prev, out_h, out_C);

    // ---- Phase 2b: gate GEMMs n-tiles 8-15 + gates rows>=512 ----
    mma_kernel<<<dim3(8, 14), 256, SMEM_TOTAL>>>(1, 8, x, h_prev, Wi, Wf, Wo, Wk, Wv, Wq);
    gates_half_kernel<<<128, 256>>>(1, n_prev, bi, bf, bo, bv, be, out_n);
    cudaEventRecord(evB, 0);

    // ---- update rows>=512 on s1 (after 2b and after first update half) ----
    cudaStreamWaitEvent(s1, evB, 0);
    update3_half_kernel<<<dim3(32, 64), 256, 0, s1>>>(1, C_prev, out_h, out_C);

    // ---- join ----
    cudaEventRecord(evC, s1);
    cudaStreamWaitEvent(0, evC, 0);
}